// round 6
// baseline (speedup 1.0000x reference)
#include <cuda_runtime.h>
#include <cuda_bf16.h>
#include <cstdint>

#define NN 100000
#define EE 1250000
#define DD 64
#define NB ((NN + 255) / 256)   // 391 scan blocks

// ---------------------------------------------------------------------------
// Scratch (__device__ globals; zero-initialized at load; self-restoring)
// ---------------------------------------------------------------------------
__device__ int   g_cnt[NN];                // edge count per dst (cleared by scan1)
__device__ float g_dis[NN];                // deg^{-1/2}
__device__ int   g_rowptr[NN];             // local-exclusive after scan1; local-inclusive after reorder
__device__ int   g_bsum[NB];               // block totals (scan1)
__device__ int   g_bsumx[NB];              // exclusive block offsets (scan2)
__device__ int2  g_epair[EE];              // (src, w-bits), dst-grouped
__device__ float g_h[NN * DD];             // feature buffer A
__device__ float g_agg[NN * DD];           // feature buffer B
__device__ int   g_dummyv;

__global__ void k_dummy() { if (threadIdx.x == 0) g_dummyv = 1; }

// ---------------------------------------------------------------------------
// Histogram: int count only, 4 edges/thread (vectorized dst load).
// ---------------------------------------------------------------------------
__global__ void k_hist(const int* __restrict__ dst) {
    int t = blockIdx.x * blockDim.x + threadIdx.x;
    int e = t * 4;
    if (e + 4 <= EE) {
        int4 d = *reinterpret_cast<const int4*>(dst + e);
        atomicAdd(&g_cnt[d.x], 1);
        atomicAdd(&g_cnt[d.y], 1);
        atomicAdd(&g_cnt[d.z], 1);
        atomicAdd(&g_cnt[d.w], 1);
    } else {
        for (; e < EE; e++) atomicAdd(&g_cnt[dst[e]], 1);
    }
}

// ---------------------------------------------------------------------------
// scan1: read+clear cnt, block-local exclusive scan.
// ---------------------------------------------------------------------------
__global__ void k_scan1() {
    __shared__ int sh[256];
    int t = threadIdx.x;
    int i = blockIdx.x * 256 + t;
    int cnt = 0;
    if (i < NN) {
        cnt = g_cnt[i];
        g_cnt[i] = 0;                                  // restore for next run
    }
    sh[t] = cnt;
    __syncthreads();
    for (int off = 1; off < 256; off <<= 1) {
        int u = (t >= off) ? sh[t - off] : 0;
        __syncthreads();
        sh[t] += u;
        __syncthreads();
    }
    if (i < NN) g_rowptr[i] = sh[t] - cnt;             // local exclusive
    if (t == 255) g_bsum[blockIdx.x] = sh[255];
}

// scan2: exclusive scan of 391 block totals -> g_bsumx
__global__ void k_scan2() {
    __shared__ int sh[512];
    int t = threadIdx.x;
    int v = (t < NB) ? g_bsum[t] : 0;
    sh[t] = v;
    __syncthreads();
    for (int off = 1; off < 512; off <<= 1) {
        int u = (t >= off) ? sh[t - off] : 0;
        __syncthreads();
        sh[t] += u;
        __syncthreads();
    }
    if (t < NB) g_bsumx[t] = sh[t] - v;
}

// ---------------------------------------------------------------------------
// Reorder: place (src, w-bits); no dis dependency.
// ---------------------------------------------------------------------------
__global__ void k_reorder(const int* __restrict__ src, const int* __restrict__ dst,
                          const float* __restrict__ w) {
    int e = blockIdx.x * blockDim.x + threadIdx.x;
    if (e >= EE) return;
    int d = dst[e];
    int pos = g_bsumx[d >> 8] + atomicAdd(&g_rowptr[d], 1);
    g_epair[pos] = make_int2(src[e], __float_as_int(w[e]));
}

// ---------------------------------------------------------------------------
// Weighted degree by CSR row-sum (no atomics): dis[n] = rsqrt(sum_w + 1)
// One warp per node.
// ---------------------------------------------------------------------------
__global__ void k_deg() {
    int n = (blockIdx.x * blockDim.x + threadIdx.x) >> 5;
    if (n >= NN) return;
    int lane = threadIdx.x & 31;
    int beg = (n == 0) ? 0 : (g_rowptr[n - 1] + g_bsumx[(n - 1) >> 8]);
    int end = g_rowptr[n] + g_bsumx[n >> 8];
    float s = 0.0f;
    for (int j = beg + lane; j < end; j += 32)
        s += __int_as_float(g_epair[j].y);
#pragma unroll
    for (int off = 16; off > 0; off >>= 1)
        s += __shfl_xor_sync(0xffffffffu, s, off);
    if (lane == 0) g_dis[n] = rsqrtf(s + 1.0f);
}

// ---------------------------------------------------------------------------
// GEMM: H[n][o] = sum_k X[n][k] * W[o][k]
// ---------------------------------------------------------------------------
__global__ void k_gemm(const float* __restrict__ X, const float* __restrict__ W,
                       float* __restrict__ H) {
    __shared__ float Ws[DD][DD];      // Ws[k][o] = W[o][k]
    __shared__ float Xs[32][DD + 1];

    int tid = threadIdx.x;
    int row0 = blockIdx.x * 32;

    for (int idx = tid; idx < DD * DD; idx += 256) {
        int o = idx / DD, k = idx % DD;
        Ws[k][o] = W[o * DD + k];
    }
    for (int idx = tid; idx < 32 * DD; idx += 256) {
        int r = idx / DD, k = idx % DD;
        Xs[r][k] = X[(size_t)(row0 + r) * DD + k];
    }
    __syncthreads();

    int r = tid >> 3;
    int j = (tid & 7) * 8;

    float acc[8];
#pragma unroll
    for (int i = 0; i < 8; i++) acc[i] = 0.0f;

#pragma unroll 8
    for (int k = 0; k < DD; k++) {
        float xv = Xs[r][k];
        float4 w0 = *reinterpret_cast<const float4*>(&Ws[k][j]);
        float4 w1 = *reinterpret_cast<const float4*>(&Ws[k][j + 4]);
        acc[0] = fmaf(xv, w0.x, acc[0]);
        acc[1] = fmaf(xv, w0.y, acc[1]);
        acc[2] = fmaf(xv, w0.z, acc[2]);
        acc[3] = fmaf(xv, w0.w, acc[3]);
        acc[4] = fmaf(xv, w1.x, acc[4]);
        acc[5] = fmaf(xv, w1.y, acc[5]);
        acc[6] = fmaf(xv, w1.z, acc[6]);
        acc[7] = fmaf(xv, w1.w, acc[7]);
    }

    float* hp = H + (size_t)(row0 + r) * DD + j;
    *reinterpret_cast<float4*>(hp)     = make_float4(acc[0], acc[1], acc[2], acc[3]);
    *reinterpret_cast<float4*>(hp + 4) = make_float4(acc[4], acc[5], acc[6], acc[7]);
}

// ---------------------------------------------------------------------------
// CSR gather, 1 warp/node, float2/lane, 8-edge prefetched batches.
// coef computed inline: dis[src] * w * dis[n].
// ---------------------------------------------------------------------------
__global__ void k_gather(const float* __restrict__ H, float* __restrict__ OUT,
                         const float* __restrict__ b, int do_relu) {
    int n = (blockIdx.x * blockDim.x + threadIdx.x) >> 5;
    if (n >= NN) return;
    int lane = threadIdx.x & 31;
    const float2* __restrict__ H2 = reinterpret_cast<const float2*>(H);

    int beg = (n == 0) ? 0 : (g_rowptr[n - 1] + g_bsumx[(n - 1) >> 8]);
    int end = g_rowptr[n] + g_bsumx[n >> 8];
    float dn = g_dis[n];

    float2 a0 = make_float2(0.f, 0.f), a1 = a0, a2 = a0, a3 = a0;

    int2 p[8];
#pragma unroll
    for (int j = 0; j < 8; j++)
        p[j] = (beg + j < end) ? g_epair[beg + j] : make_int2(0, 0);

    int e = beg;
    while (e + 8 <= end) {
        float ds[8];
        float2 f[8];
#pragma unroll
        for (int j = 0; j < 8; j++) {
            ds[j] = g_dis[p[j].x];
            f[j] = H2[((size_t)p[j].x << 5) + lane];
        }

        int2 np[8];
#pragma unroll
        for (int j = 0; j < 8; j++)
            np[j] = (e + 8 + j < end) ? g_epair[e + 8 + j] : make_int2(0, 0);

#pragma unroll
        for (int j = 0; j < 8; j++) {
            float c = ds[j] * __int_as_float(p[j].y) * dn;
            float2* a = (j & 3) == 0 ? &a0 : (j & 3) == 1 ? &a1 : (j & 3) == 2 ? &a2 : &a3;
            a->x = fmaf(c, f[j].x, a->x);
            a->y = fmaf(c, f[j].y, a->y);
        }
#pragma unroll
        for (int j = 0; j < 8; j++) p[j] = np[j];
        e += 8;
    }

    int rem = end - e;
#pragma unroll
    for (int j = 0; j < 8; j++) {
        if (j < rem) {
            float c = g_dis[p[j].x] * __int_as_float(p[j].y) * dn;
            float2 f = H2[((size_t)p[j].x << 5) + lane];
            float2* a = (j & 3) == 0 ? &a0 : (j & 3) == 1 ? &a1 : (j & 3) == 2 ? &a2 : &a3;
            a->x = fmaf(c, f.x, a->x);
            a->y = fmaf(c, f.y, a->y);
        }
    }

    float2 hs = H2[((size_t)n << 5) + lane];
    float2 bv = reinterpret_cast<const float2*>(b)[lane];
    float s2 = dn * dn;

    float ox = (a0.x + a1.x) + (a2.x + a3.x) + hs.x * s2 + bv.x;
    float oy = (a0.y + a1.y) + (a2.y + a3.y) + hs.y * s2 + bv.y;
    if (do_relu) { ox = fmaxf(ox, 0.f); oy = fmaxf(oy, 0.f); }
    reinterpret_cast<float2*>(OUT)[((size_t)n << 5) + lane] = make_float2(ox, oy);
}

// ---------------------------------------------------------------------------
// Launch (k_hist at position #4 -> profiled by ncu)
// ---------------------------------------------------------------------------
extern "C" void kernel_launch(void* const* d_in, const int* in_sizes, int n_in,
                              void* d_out, int out_size) {
    const float* x  = (const float*)d_in[0];
    const int*   ei = (const int*)d_in[1];
    const float* w  = (const float*)d_in[2];
    const float* W1 = (const float*)d_in[3];
    const float* b1 = (const float*)d_in[4];
    const float* W2 = (const float*)d_in[5];
    const float* b2 = (const float*)d_in[6];
    float* out = (float*)d_out;

    const int* src = ei;
    const int* dst = ei + EE;

    float* h_p;   cudaGetSymbolAddress((void**)&h_p,   g_h);
    float* agg_p; cudaGetSymbolAddress((void**)&agg_p, g_agg);

    const int T = 256;
    int bE  = (EE + T - 1) / T;                // 4883
    int bE4 = (EE / 4 + T - 1) / T;            // 1221
    int bG  = NN / 32;                         // 3125
    int bW  = (NN * 32 + T - 1) / T;           // 12500 (1 warp/node)

    k_gemm<<<bG, T>>>(x, W1, h_p);             // #1 (independent)
    k_dummy<<<1, 32>>>();                      // #2
    k_dummy<<<1, 32>>>();                      // #3
    k_hist<<<bE4, T>>>(dst);                   // #4  <-- profiled
    k_scan1<<<NB, 256>>>();                    // #5
    k_scan2<<<1, 512>>>();                     // #6
    k_reorder<<<bE, T>>>(src, dst, w);         // #7
    k_deg<<<bW, T>>>();                        // #8
    k_gather<<<bW, T>>>(h_p, agg_p, b1, 1);    // #9
    k_gemm<<<bG, T>>>(agg_p, W2, h_p);         // #10
    k_gather<<<bW, T>>>(h_p, out, b2, 0);      // #11
}

// round 7
// speedup vs baseline: 1.9090x; 1.9090x over previous
#include <cuda_runtime.h>
#include <cuda_bf16.h>
#include <cstdint>

#define NN 100000
#define EE 1250000
#define DD 64
#define NB ((NN + 255) / 256)   // 391 scan blocks

// ---------------------------------------------------------------------------
// Scratch (__device__ globals; zero-initialized at load; self-restoring)
// ---------------------------------------------------------------------------
__device__ int   g_cnt[NN];                // edge count per dst (cleared by scan1)
__device__ float g_dis[NN];                // deg^{-1/2}
__device__ int   g_rowptr[NN];             // local-exclusive after scan1; local-inclusive after reorder
__device__ int   g_bsum[NB];               // block totals (scan1)
__device__ int   g_bsumx[NB];              // exclusive block offsets (scan2)
__device__ int2  g_epair[EE];              // (src, w-bits) after reorder; (src, coef-bits) after k_coef
__device__ float g_h[NN * DD];             // feature buffer A
__device__ float g_agg[NN * DD];           // feature buffer B

// ---------------------------------------------------------------------------
// Histogram: int count, 4 edges/thread.
// ---------------------------------------------------------------------------
__global__ void k_hist(const int* __restrict__ dst) {
    int t = blockIdx.x * blockDim.x + threadIdx.x;
    int e = t * 4;
    if (e + 4 <= EE) {
        int4 d = *reinterpret_cast<const int4*>(dst + e);
        atomicAdd(&g_cnt[d.x], 1);
        atomicAdd(&g_cnt[d.y], 1);
        atomicAdd(&g_cnt[d.z], 1);
        atomicAdd(&g_cnt[d.w], 1);
    } else {
        for (; e < EE; e++) atomicAdd(&g_cnt[dst[e]], 1);
    }
}

// ---------------------------------------------------------------------------
// scan1: read+clear cnt, block-local exclusive scan.
// ---------------------------------------------------------------------------
__global__ void k_scan1() {
    __shared__ int sh[256];
    int t = threadIdx.x;
    int i = blockIdx.x * 256 + t;
    int cnt = 0;
    if (i < NN) {
        cnt = g_cnt[i];
        g_cnt[i] = 0;                                  // restore for next run
    }
    sh[t] = cnt;
    __syncthreads();
    for (int off = 1; off < 256; off <<= 1) {
        int u = (t >= off) ? sh[t - off] : 0;
        __syncthreads();
        sh[t] += u;
        __syncthreads();
    }
    if (i < NN) g_rowptr[i] = sh[t] - cnt;             // local exclusive
    if (t == 255) g_bsum[blockIdx.x] = sh[255];
}

// scan2: exclusive scan of 391 block totals -> g_bsumx
__global__ void k_scan2() {
    __shared__ int sh[512];
    int t = threadIdx.x;
    int v = (t < NB) ? g_bsum[t] : 0;
    sh[t] = v;
    __syncthreads();
    for (int off = 1; off < 512; off <<= 1) {
        int u = (t >= off) ? sh[t - off] : 0;
        __syncthreads();
        sh[t] += u;
        __syncthreads();
    }
    if (t < NB) g_bsumx[t] = sh[t] - v;
}

// ---------------------------------------------------------------------------
// Reorder: place (src, w-bits).
// ---------------------------------------------------------------------------
__global__ void k_reorder(const int* __restrict__ src, const int* __restrict__ dst,
                          const float* __restrict__ w) {
    int e = blockIdx.x * blockDim.x + threadIdx.x;
    if (e >= EE) return;
    int d = dst[e];
    int pos = g_bsumx[d >> 8] + atomicAdd(&g_rowptr[d], 1);
    g_epair[pos] = make_int2(src[e], __float_as_int(w[e]));
}

// ---------------------------------------------------------------------------
// Weighted degree by CSR row-sum: dis[n] = rsqrt(sum_w + 1). One warp/node.
// ---------------------------------------------------------------------------
__global__ void k_deg() {
    int n = (blockIdx.x * blockDim.x + threadIdx.x) >> 5;
    if (n >= NN) return;
    int lane = threadIdx.x & 31;
    int beg = (n == 0) ? 0 : (g_rowptr[n - 1] + g_bsumx[(n - 1) >> 8]);
    int end = g_rowptr[n] + g_bsumx[n >> 8];
    float s = 0.0f;
    for (int j = beg + lane; j < end; j += 32)
        s += __int_as_float(g_epair[j].y);
#pragma unroll
    for (int off = 16; off > 0; off >>= 1)
        s += __shfl_xor_sync(0xffffffffu, s, off);
    if (lane == 0) g_dis[n] = rsqrtf(s + 1.0f);
}

// ---------------------------------------------------------------------------
// Coef: epair[j].y = dis[src] * w * dis[n], in CSR order. One warp/node.
// ---------------------------------------------------------------------------
__global__ void k_coef() {
    int n = (blockIdx.x * blockDim.x + threadIdx.x) >> 5;
    if (n >= NN) return;
    int lane = threadIdx.x & 31;
    int beg = (n == 0) ? 0 : (g_rowptr[n - 1] + g_bsumx[(n - 1) >> 8]);
    int end = g_rowptr[n] + g_bsumx[n >> 8];
    float dn = g_dis[n];
    for (int j = beg + lane; j < end; j += 32) {
        int2 p = g_epair[j];
        float c = g_dis[p.x] * __int_as_float(p.y) * dn;
        g_epair[j].y = __float_as_int(c);
    }
}

// ---------------------------------------------------------------------------
// Register-blocked GEMM: H[n][o] = sum_k X[n][k] * W[o][k]
// Block: 256 threads, 128-row x 64-col output tile, 4x8 outputs/thread.
// ---------------------------------------------------------------------------
__global__ void __launch_bounds__(256) k_gemm(const float* __restrict__ X,
                                              const float* __restrict__ W,
                                              float* __restrict__ H) {
    __shared__ float Xs[128][65];     // pad 65: bank(r,k) = (r+k)%32 -> conflict-free
    __shared__ float Ws[DD][DD];      // Ws[k][o] = W[o][k]

    int tid = threadIdx.x;
    int lane = tid & 31;              // row within 32-row group
    int grp  = tid >> 5;              // 0..7 -> col group
    int row0 = blockIdx.x * 128;

    // Load W transposed: 4096 elems, 16/thread (float4 global, scalar STS)
    for (int idx = tid; idx < (DD * DD) / 4; idx += 256) {
        int o = idx >> 4;             // 0..63
        int k4 = (idx & 15) * 4;
        float4 v = *reinterpret_cast<const float4*>(W + o * DD + k4);
        Ws[k4 + 0][o] = v.x;
        Ws[k4 + 1][o] = v.y;
        Ws[k4 + 2][o] = v.z;
        Ws[k4 + 3][o] = v.w;
    }
    // Load 128 rows of X: 8192 elems, float4 global, scalar STS (pad-65)
    for (int idx = tid; idx < (128 * DD) / 4; idx += 256) {
        int r = idx >> 4;
        int k4 = (idx & 15) * 4;
        int row = row0 + r;
        float4 v = (row < NN) ? *reinterpret_cast<const float4*>(X + (size_t)row * DD + k4)
                              : make_float4(0.f, 0.f, 0.f, 0.f);
        Xs[r][k4 + 0] = v.x;
        Xs[r][k4 + 1] = v.y;
        Xs[r][k4 + 2] = v.z;
        Xs[r][k4 + 3] = v.w;
    }
    __syncthreads();

    int c0 = grp * 8;
    float acc[4][8];
#pragma unroll
    for (int i = 0; i < 4; i++)
#pragma unroll
        for (int j = 0; j < 8; j++) acc[i][j] = 0.0f;

#pragma unroll 4
    for (int k = 0; k < DD; k++) {
        float xv0 = Xs[lane      ][k];
        float xv1 = Xs[lane + 32 ][k];
        float xv2 = Xs[lane + 64 ][k];
        float xv3 = Xs[lane + 96 ][k];
        float4 w0 = *reinterpret_cast<const float4*>(&Ws[k][c0]);
        float4 w1 = *reinterpret_cast<const float4*>(&Ws[k][c0 + 4]);
        float wv[8] = {w0.x, w0.y, w0.z, w0.w, w1.x, w1.y, w1.z, w1.w};
#pragma unroll
        for (int j = 0; j < 8; j++) {
            acc[0][j] = fmaf(xv0, wv[j], acc[0][j]);
            acc[1][j] = fmaf(xv1, wv[j], acc[1][j]);
            acc[2][j] = fmaf(xv2, wv[j], acc[2][j]);
            acc[3][j] = fmaf(xv3, wv[j], acc[3][j]);
        }
    }

#pragma unroll
    for (int i = 0; i < 4; i++) {
        int row = row0 + lane + i * 32;
        if (row < NN) {
            float* hp = H + (size_t)row * DD + c0;
            *reinterpret_cast<float4*>(hp)     = make_float4(acc[i][0], acc[i][1], acc[i][2], acc[i][3]);
            *reinterpret_cast<float4*>(hp + 4) = make_float4(acc[i][4], acc[i][5], acc[i][6], acc[i][7]);
        }
    }
}

// ---------------------------------------------------------------------------
// CSR gather, 1 warp/node, float2/lane, 8-edge prefetched batches.
// epair holds (src, coef-bits).
// ---------------------------------------------------------------------------
__global__ void k_gather(const float* __restrict__ H, float* __restrict__ OUT,
                         const float* __restrict__ b, int do_relu) {
    int n = (blockIdx.x * blockDim.x + threadIdx.x) >> 5;
    if (n >= NN) return;
    int lane = threadIdx.x & 31;
    const float2* __restrict__ H2 = reinterpret_cast<const float2*>(H);

    int beg = (n == 0) ? 0 : (g_rowptr[n - 1] + g_bsumx[(n - 1) >> 8]);
    int end = g_rowptr[n] + g_bsumx[n >> 8];

    float2 a0 = make_float2(0.f, 0.f), a1 = a0, a2 = a0, a3 = a0;

    int2 p[8];
#pragma unroll
    for (int j = 0; j < 8; j++)
        p[j] = (beg + j < end) ? g_epair[beg + j] : make_int2(0, 0);

    int e = beg;
    while (e + 8 <= end) {
        float2 f[8];
#pragma unroll
        for (int j = 0; j < 8; j++)
            f[j] = H2[((size_t)p[j].x << 5) + lane];

        int2 np[8];
#pragma unroll
        for (int j = 0; j < 8; j++)
            np[j] = (e + 8 + j < end) ? g_epair[e + 8 + j] : make_int2(0, 0);

#pragma unroll
        for (int j = 0; j < 8; j++) {
            float c = __int_as_float(p[j].y);
            float2* a = (j & 3) == 0 ? &a0 : (j & 3) == 1 ? &a1 : (j & 3) == 2 ? &a2 : &a3;
            a->x = fmaf(c, f[j].x, a->x);
            a->y = fmaf(c, f[j].y, a->y);
        }
#pragma unroll
        for (int j = 0; j < 8; j++) p[j] = np[j];
        e += 8;
    }

    int rem = end - e;
#pragma unroll
    for (int j = 0; j < 8; j++) {
        if (j < rem) {
            float2 f = H2[((size_t)p[j].x << 5) + lane];
            float c = __int_as_float(p[j].y);
            float2* a = (j & 3) == 0 ? &a0 : (j & 3) == 1 ? &a1 : (j & 3) == 2 ? &a2 : &a3;
            a->x = fmaf(c, f.x, a->x);
            a->y = fmaf(c, f.y, a->y);
        }
    }

    float dn = g_dis[n];
    float s2 = dn * dn;
    float2 hs = H2[((size_t)n << 5) + lane];
    float2 bv = reinterpret_cast<const float2*>(b)[lane];

    float ox = (a0.x + a1.x) + (a2.x + a3.x) + hs.x * s2 + bv.x;
    float oy = (a0.y + a1.y) + (a2.y + a3.y) + hs.y * s2 + bv.y;
    if (do_relu) { ox = fmaxf(ox, 0.f); oy = fmaxf(oy, 0.f); }
    reinterpret_cast<float2*>(OUT)[((size_t)n << 5) + lane] = make_float2(ox, oy);
}

// ---------------------------------------------------------------------------
// Launch (k_gemm at position #4 -> profiled by ncu)
// ---------------------------------------------------------------------------
extern "C" void kernel_launch(void* const* d_in, const int* in_sizes, int n_in,
                              void* d_out, int out_size) {
    const float* x  = (const float*)d_in[0];
    const int*   ei = (const int*)d_in[1];
    const float* w  = (const float*)d_in[2];
    const float* W1 = (const float*)d_in[3];
    const float* b1 = (const float*)d_in[4];
    const float* W2 = (const float*)d_in[5];
    const float* b2 = (const float*)d_in[6];
    float* out = (float*)d_out;

    const int* src = ei;
    const int* dst = ei + EE;

    float* h_p;   cudaGetSymbolAddress((void**)&h_p,   g_h);
    float* agg_p; cudaGetSymbolAddress((void**)&agg_p, g_agg);

    const int T = 256;
    int bE  = (EE + T - 1) / T;                // 4883
    int bE4 = (EE / 4 + T - 1) / T;            // 1221
    int bG  = (NN + 127) / 128;                // 782
    int bW  = (NN * 32 + T - 1) / T;           // 12500 (1 warp/node)

    k_hist<<<bE4, T>>>(dst);                   // #1
    k_scan1<<<NB, 256>>>();                    // #2
    k_scan2<<<1, 512>>>();                     // #3
    k_gemm<<<bG, T>>>(x, W1, h_p);             // #4  <-- profiled (independent of build)
    k_reorder<<<bE, T>>>(src, dst, w);         // #5
    k_deg<<<bW, T>>>();                        // #6
    k_coef<<<bW, T>>>();                       // #7
    k_gather<<<bW, T>>>(h_p, agg_p, b1, 1);    // #8
    k_gemm<<<bG, T>>>(agg_p, W2, h_p);         // #9
    k_gather<<<bW, T>>>(h_p, out, b2, 0);      // #10
}